// round 3
// baseline (speedup 1.0000x reference)
#include <cuda_runtime.h>
#include <math.h>
#include <stdint.h>

#define N_CTX   4096
#define D_MODEL 2048

// Scratch (allocation-free rule: __device__ globals)
__device__ float g_xb[(size_t)N_CTX * D_MODEL];
__device__ float g_xs[(size_t)N_CTX * D_MODEL];
__device__ float g_wqkb[(size_t)D_MODEL * D_MODEL];
__device__ float g_wqks[(size_t)D_MODEL * D_MODEL];
__device__ float g_wovb[(size_t)D_MODEL * D_MODEL];
__device__ float g_Qb[(size_t)N_CTX * D_MODEL];
__device__ float g_Qs[(size_t)N_CTX * D_MODEL];
__device__ float g_S [(size_t)N_CTX * N_CTX];
__device__ float g_A [(size_t)N_CTX * D_MODEL];

// ---------------------------------------------------------------------------
// helpers
// ---------------------------------------------------------------------------
__device__ __forceinline__ float f2tf32f(float x) {
    uint32_t r;
    asm("cvt.rna.tf32.f32 %0, %1;" : "=r"(r) : "f"(x));
    return __uint_as_float(r);
}

__device__ __forceinline__ void mma_tf32(float c[4],
                                         float a0, float a1, float a2, float a3,
                                         float b0, float b1) {
    asm volatile(
        "mma.sync.aligned.m16n8k8.row.col.f32.tf32.tf32.f32 "
        "{%0,%1,%2,%3}, {%4,%5,%6,%7}, {%8,%9}, {%0,%1,%2,%3};"
        : "+f"(c[0]), "+f"(c[1]), "+f"(c[2]), "+f"(c[3])
        : "r"(__float_as_uint(a0)), "r"(__float_as_uint(a1)),
          "r"(__float_as_uint(a2)), "r"(__float_as_uint(a3)),
          "r"(__float_as_uint(b0)), "r"(__float_as_uint(b1)));
}

__device__ __forceinline__ void cp_async16(void* smem, const void* gmem) {
    uint32_t s = (uint32_t)__cvta_generic_to_shared(smem);
    asm volatile("cp.async.cg.shared.global [%0], [%1], 16;" :: "r"(s), "l"(gmem));
}
__device__ __forceinline__ void cp_async4(void* smem, const void* gmem) {
    uint32_t s = (uint32_t)__cvta_generic_to_shared(smem);
    asm volatile("cp.async.ca.shared.global [%0], [%1], 4;" :: "r"(s), "l"(gmem));
}

// ---------------------------------------------------------------------------
// Elementwise pre-conversion kernels (memory-bound, run every launch)
// ---------------------------------------------------------------------------
__global__ __launch_bounds__(256)
void split_tf32_kernel(const float* __restrict__ src,
                       float* __restrict__ big, float* __restrict__ sml, int n4)
{
    int i = blockIdx.x * 256 + threadIdx.x;
    if (i >= n4) return;
    float4 v = ((const float4*)src)[i];
    float4 b, s;
    b.x = f2tf32f(v.x); s.x = f2tf32f(v.x - b.x);
    b.y = f2tf32f(v.y); s.y = f2tf32f(v.y - b.y);
    b.z = f2tf32f(v.z); s.z = f2tf32f(v.z - b.z);
    b.w = f2tf32f(v.w); s.w = f2tf32f(v.w - b.w);
    ((float4*)big)[i] = b;
    ((float4*)sml)[i] = s;
}

__global__ __launch_bounds__(256)
void round_tf32_kernel(const float* __restrict__ src, float* __restrict__ dst, int n4)
{
    int i = blockIdx.x * 256 + threadIdx.x;
    if (i >= n4) return;
    float4 v = ((const float4*)src)[i];
    v.x = f2tf32f(v.x); v.y = f2tf32f(v.y); v.z = f2tf32f(v.z); v.w = f2tf32f(v.w);
    ((float4*)dst)[i] = v;
}

// ---------------------------------------------------------------------------
// tf32 tensor-core GEMM:  C[M,N] = A[M,K] @ op(B)
//   TRANS_B=1: B is [N,K] (C = A @ B^T);  TRANS_B=0: B is [K,N]
//   CSKIP: skip blocks fully above diagonal;  CK: limit k-loop to m0+BM
//   SPLIT: 3xTF32 error compensation using pre-split big/small operands
//   EPI: 0 = plain fp32 store; 1 = split store (big->C, small->C2);
//        2 = tf32-rounded store
// Block 128x128x16, 8 warps (2x4), warp tile 64x32, m16n8k8.
// ---------------------------------------------------------------------------
template <int TRANS_B, int CSKIP, int CK, int SPLIT, int OCC, int EPI>
__global__ __launch_bounds__(256, OCC)
void mma_gemm(const float* __restrict__ Abig, const float* __restrict__ Asml,
              const float* __restrict__ Bbig, const float* __restrict__ Bsml,
              float* __restrict__ C, float* __restrict__ C2,
              int M, int N, int K)
{
    constexpr int BM = 128, BN = 128, BK = 16, LDP = 20;
    constexpr int BMs = SPLIT ? BM : 1;
    constexpr int BNs = SPLIT ? BN : 1;

    __shared__ float sA [2][BM][LDP];
    __shared__ float sB [2][BN][LDP];
    __shared__ float sAm[2][BMs][LDP];   // small terms (SPLIT only)
    __shared__ float sBm[2][BNs][LDP];

    const int m0 = blockIdx.y * BM;
    const int n0 = blockIdx.x * BN;
    if (CSKIP && n0 >= m0 + BM) return;

    const int kEnd = CK ? min(K, m0 + BM) : K;
    const int nK   = kEnd / BK;

    const int tid  = threadIdx.x;
    const int warp = tid >> 5;
    const int lane = tid & 31;
    const int wm0  = (warp & 1) * 64;
    const int wn0  = (warp >> 1) * 32;
    const int g    = lane >> 2;
    const int tg   = lane & 3;

    float acc[4][4][4];
    #pragma unroll
    for (int i = 0; i < 4; i++)
        #pragma unroll
        for (int j = 0; j < 4; j++)
            #pragma unroll
            for (int r = 0; r < 4; r++) acc[i][j][r] = 0.0f;

    auto loadStage = [&](int buf, int k0) {
        #pragma unroll
        for (int i = 0; i < 2; i++) {
            int idx = tid + i * 256;
            int row = idx >> 2;
            int c4  = (idx & 3) * 4;
            cp_async16(&sA[buf][row][c4], Abig + (size_t)(m0 + row) * K + k0 + c4);
            if constexpr (SPLIT)
                cp_async16(&sAm[buf][row][c4], Asml + (size_t)(m0 + row) * K + k0 + c4);
        }
        if (TRANS_B) {
            #pragma unroll
            for (int i = 0; i < 2; i++) {
                int idx = tid + i * 256;
                int row = idx >> 2;
                int c4  = (idx & 3) * 4;
                cp_async16(&sB[buf][row][c4], Bbig + (size_t)(n0 + row) * K + k0 + c4);
                if constexpr (SPLIT)
                    cp_async16(&sBm[buf][row][c4], Bsml + (size_t)(n0 + row) * K + k0 + c4);
            }
        } else {
            #pragma unroll
            for (int i = 0; i < 8; i++) {
                int e = tid + i * 256;
                int k = e >> 7;
                int n = e & 127;
                cp_async4(&sB[buf][n][k], Bbig + (size_t)(k0 + k) * N + n0 + n);
            }
        }
    };

    auto compute = [&](int buf) {
        #pragma unroll
        for (int ks = 0; ks < 2; ks++) {
            const int kb = ks * 8;
            float Ab[4][4], Am[4][4];
            float Bb[4][2], Bm[4][2];

            #pragma unroll
            for (int mt = 0; mt < 4; mt++) {
                Ab[mt][0] = sA[buf][wm0 + mt * 16 + g    ][kb + tg    ];
                Ab[mt][1] = sA[buf][wm0 + mt * 16 + g + 8][kb + tg    ];
                Ab[mt][2] = sA[buf][wm0 + mt * 16 + g    ][kb + tg + 4];
                Ab[mt][3] = sA[buf][wm0 + mt * 16 + g + 8][kb + tg + 4];
                if constexpr (SPLIT) {
                    Am[mt][0] = sAm[buf][wm0 + mt * 16 + g    ][kb + tg    ];
                    Am[mt][1] = sAm[buf][wm0 + mt * 16 + g + 8][kb + tg    ];
                    Am[mt][2] = sAm[buf][wm0 + mt * 16 + g    ][kb + tg + 4];
                    Am[mt][3] = sAm[buf][wm0 + mt * 16 + g + 8][kb + tg + 4];
                }
            }
            #pragma unroll
            for (int nt = 0; nt < 4; nt++) {
                Bb[nt][0] = sB[buf][wn0 + nt * 8 + g][kb + tg    ];
                Bb[nt][1] = sB[buf][wn0 + nt * 8 + g][kb + tg + 4];
                if constexpr (SPLIT) {
                    Bm[nt][0] = sBm[buf][wn0 + nt * 8 + g][kb + tg    ];
                    Bm[nt][1] = sBm[buf][wn0 + nt * 8 + g][kb + tg + 4];
                }
            }
            #pragma unroll
            for (int mt = 0; mt < 4; mt++) {
                #pragma unroll
                for (int nt = 0; nt < 4; nt++) {
                    if constexpr (SPLIT) {
                        mma_tf32(acc[mt][nt], Am[mt][0], Am[mt][1], Am[mt][2], Am[mt][3],
                                 Bb[nt][0], Bb[nt][1]);
                        mma_tf32(acc[mt][nt], Ab[mt][0], Ab[mt][1], Ab[mt][2], Ab[mt][3],
                                 Bm[nt][0], Bm[nt][1]);
                    }
                    mma_tf32(acc[mt][nt], Ab[mt][0], Ab[mt][1], Ab[mt][2], Ab[mt][3],
                             Bb[nt][0], Bb[nt][1]);
                }
            }
        }
    };

    loadStage(0, 0);
    asm volatile("cp.async.commit_group;" ::: "memory");

    for (int kt = 0; kt < nK; kt++) {
        if (kt + 1 < nK) {
            loadStage((kt + 1) & 1, (kt + 1) * BK);
            asm volatile("cp.async.commit_group;" ::: "memory");
            asm volatile("cp.async.wait_group 1;" ::: "memory");
        } else {
            asm volatile("cp.async.wait_group 0;" ::: "memory");
        }
        __syncthreads();
        compute(kt & 1);
        __syncthreads();
    }

    // ---- epilogue ----
    #pragma unroll
    for (int mt = 0; mt < 4; mt++) {
        #pragma unroll
        for (int nt = 0; nt < 4; nt++) {
            int r = m0 + wm0 + mt * 16 + g;
            int c = n0 + wn0 + nt * 8 + 2 * tg;
            #pragma unroll
            for (int h = 0; h < 2; h++) {
                float v0 = acc[mt][nt][h * 2 + 0];
                float v1 = acc[mt][nt][h * 2 + 1];
                size_t off = (size_t)(r + h * 8) * N + c;
                if constexpr (EPI == 0) {
                    *(float2*)(C + off) = make_float2(v0, v1);
                } else if constexpr (EPI == 1) {
                    float b0 = f2tf32f(v0), b1 = f2tf32f(v1);
                    *(float2*)(C  + off) = make_float2(b0, b1);
                    *(float2*)(C2 + off) = make_float2(f2tf32f(v0 - b0), f2tf32f(v1 - b1));
                } else {
                    *(float2*)(C + off) = make_float2(f2tf32f(v0), f2tf32f(v1));
                }
            }
        }
    }
}

// ---------------------------------------------------------------------------
// Causal row softmax, in place; output tf32-rounded. One block per row.
// ---------------------------------------------------------------------------
__global__ __launch_bounds__(256)
void softmax_kernel(float* __restrict__ S, int n)
{
    const int row   = blockIdx.x;
    float* srow     = S + (size_t)row * n;
    const int valid = row + 1;
    const int tid   = threadIdx.x;

    __shared__ float red[256];

    float m = -INFINITY;
    for (int j = tid; j < valid; j += 256) m = fmaxf(m, srow[j]);
    red[tid] = m;
    __syncthreads();
    #pragma unroll
    for (int s = 128; s > 0; s >>= 1) {
        if (tid < s) red[tid] = fmaxf(red[tid], red[tid + s]);
        __syncthreads();
    }
    m = red[0];
    __syncthreads();

    float sum = 0.0f;
    for (int j = tid; j < valid; j += 256) {
        float e = __expf(srow[j] - m);
        srow[j] = e;                 // stash exp, avoid recompute
        sum += e;
    }
    red[tid] = sum;
    __syncthreads();
    #pragma unroll
    for (int s = 128; s > 0; s >>= 1) {
        if (tid < s) red[tid] += red[tid + s];
        __syncthreads();
    }
    const float inv = 1.0f / red[0];

    for (int j = tid; j < n; j += 256)
        srow[j] = (j < valid) ? f2tf32f(srow[j] * inv) : 0.0f;
}

// ---------------------------------------------------------------------------
extern "C" void kernel_launch(void* const* d_in, const int* in_sizes, int n_in,
                              void* d_out, int out_size)
{
    const float* x   = (const float*)d_in[0];
    const float* Wqk = (const float*)d_in[1];
    const float* Wov = (const float*)d_in[2];
    float* out       = (float*)d_out;

    float *xb, *xs, *wqkb, *wqks, *wovb, *Qb, *Qs, *S, *A;
    cudaGetSymbolAddress((void**)&xb,   g_xb);
    cudaGetSymbolAddress((void**)&xs,   g_xs);
    cudaGetSymbolAddress((void**)&wqkb, g_wqkb);
    cudaGetSymbolAddress((void**)&wqks, g_wqks);
    cudaGetSymbolAddress((void**)&wovb, g_wovb);
    cudaGetSymbolAddress((void**)&Qb,   g_Qb);
    cudaGetSymbolAddress((void**)&Qs,   g_Qs);
    cudaGetSymbolAddress((void**)&S,    g_S);
    cudaGetSymbolAddress((void**)&A,    g_A);

    const int nx4 = N_CTX * D_MODEL / 4;
    const int nw4 = D_MODEL * D_MODEL / 4;

    // Pre-split / pre-round operands (hoists all cvt out of GEMM mainloops)
    split_tf32_kernel<<<(nx4 + 255) / 256, 256>>>(x, xb, xs, nx4);
    split_tf32_kernel<<<(nw4 + 255) / 256, 256>>>(Wqk, wqkb, wqks, nw4);
    round_tf32_kernel<<<(nw4 + 255) / 256, 256>>>(Wov, wovb, nw4);

    // 1) Q = x @ Wqk^T  (3xTF32; epilogue writes split Qb/Qs)
    mma_gemm<1, 0, 0, 1, 1, 1><<<dim3(D_MODEL / 128, N_CTX / 128), 256>>>(
        xb, xs, wqkb, wqks, Qb, Qs, N_CTX, D_MODEL, D_MODEL);

    // 2) S = Q @ x^T  (causal blocks only, 3xTF32)
    mma_gemm<1, 1, 0, 1, 1, 0><<<dim3(N_CTX / 128, N_CTX / 128), 256>>>(
        Qb, Qs, xb, xs, S, nullptr, N_CTX, N_CTX, D_MODEL);

    // 3) P = causal_softmax(S), in place, tf32-rounded
    softmax_kernel<<<N_CTX, 256>>>(S, N_CTX);

    // 4) A = P @ x  (plain tf32, causal k-limit; epilogue rounds A to tf32)
    mma_gemm<0, 0, 1, 0, 2, 2><<<dim3(D_MODEL / 128, N_CTX / 128), 256>>>(
        S, nullptr, xb, nullptr, A, nullptr, N_CTX, D_MODEL, N_CTX);

    // 5) out = A @ Wov^T  (plain tf32)
    mma_gemm<1, 0, 0, 0, 2, 0><<<dim3(D_MODEL / 128, N_CTX / 128), 256>>>(
        A, nullptr, wovb, nullptr, out, nullptr, N_CTX, D_MODEL, D_MODEL);
}